// round 17
// baseline (speedup 1.0000x reference)
#include <cuda_runtime.h>

// PolyphaseDiff: resample_poly(x, up=3, down=2), 129-tap FIR.
// out[j] = sum_c a_pf[c] * x[i0-42+c], t=64+2j, pf=t%3, i0=t/3, a_pf[c]=3h[pf+126-3c].
//
// R17: RR=12 supertile (2304 outputs/block, grid=1366, TPB=1). The smem
// crossbar is the wall (window read redundancy 2.8x at RR=8); RR=12 cuts
// window pairs/output 3.75 -> 2.83 and amortizes per-tile overheads.
//   acc[r] += T[p][k] * tq[12u + r + k], k=0..21, r=0..11  (fma.rn.f32x2)
// Tap pairing identical to R5-R16 (Jb=2304b == 0 mod 3 -> same phase folding).
// Tile pad 2-per-4 (i + 2*(i>>2)): lane base 144B (16B aligned), word stride
// 36 == 4 mod 32 -> LDS.128 conflict-free; compile-time in-loop offsets.
// Staging rows stride 37 (odd -> conflict-free STS); reader owns 12 words,
// 3 aligned STG.128.

#define RR 12
#define NP 22
#define THREADS 192          // 6 warps: warp w -> class w%3
#define NOUT_BLK 2304        // 3 * 64 * RR
#define TQ 790               // u64 pairs per tile (max pair idx 789)
#define TQ_ALLOC 1188        // 790 + 2*(790/4) + 4
#define TILE_F 1580
#define SOUT 2368            // 64 rows * 37 (36 data + 1 pad)

typedef unsigned long long u64;

#define FMA_X2(d, a, b, c) \
    asm("fma.rn.f32x2 %0, %1, %2, %3;" : "=l"(d) : "l"(a), "l"(b), "l"(c))
#define PACK_X2(d, lo, hi) \
    asm("mov.b64 %0, {%1, %2};" : "=l"(d) : "f"(lo), "f"(hi))
#define UNPACK_X2(lo, hi, s) \
    asm("mov.b64 {%0, %1}, %2;" : "=f"(lo), "=f"(hi) : "l"(s))
#define LDS_V2U64(a, b, addr32) \
    asm volatile("ld.shared.v2.b64 {%0, %1}, [%2];" : "=l"(a), "=l"(b) : "r"(addr32))
#define CP_ASYNC4(dst_u32, src_ptr) \
    asm volatile("cp.async.ca.shared.global [%0], [%1], 4;" :: "r"(dst_u32), "l"(src_ptr))
#define CP_COMMIT() asm volatile("cp.async.commit_group;" ::: "memory")
#define CP_WAIT0()  asm volatile("cp.async.wait_group 0;" ::: "memory")
#define BAR_HALF(id) asm volatile("bar.sync %0, 96;" :: "r"(id) : "memory")

// padded pair slot: 2 pad pairs per 4
__device__ __forceinline__ int SPq(int i) { return i + 2 * (i >> 2); }

__global__ __launch_bounds__(THREADS, 5)
void poly_resample_kernel(const float* __restrict__ x,
                          const float* __restrict__ h,
                          float* __restrict__ out,
                          int N, int n_out)
{
    __shared__ __align__(16) u64   sh2[TQ_ALLOC];
    __shared__ __align__(16) u64   sh_t[3 * NP];
    __shared__ __align__(16) float sh_out[SOUT];

    const int tid = threadIdx.x;
    const int tt  = blockIdx.x;
    const int Jb  = tt * NOUT_BLK;
    const int IB  = 1536 * tt - 21;

    // ---- pack taps: class p uses filter phase pf = (1+2p)%3 ----
    if (tid < 3 * NP) {
        int p = tid / NP, k = tid % NP;
        int pf = (1 + 2 * p) % 3;             // {1,0,2}
        float lo, hi;
        if (p == 0) {
            lo = 3.0f * h[127 - 6 * k];
            hi = (k < 21) ? 3.0f * h[124 - 6 * k] : 0.0f;
        } else if (k == 0) {
            lo = 0.0f;
            hi = 3.0f * h[pf + 126];
        } else {
            lo = 3.0f * h[pf + 129 - 6 * k];
            hi = 3.0f * h[pf + 126 - 6 * k];
        }
        u64 d; PACK_X2(d, lo, hi);
        sh_t[tid] = d;
    }

    // ---- tile load: cp.async fast path, guarded scalar at edges ----
    const unsigned sh2b = (unsigned)__cvta_generic_to_shared(sh2);
    if (IB >= 0 && IB + TILE_F <= N) {
        const float* src = x + IB;
        #pragma unroll
        for (int q = 0; q < 9; ++q) {
            int f = tid + q * THREADS;
            if (f < TILE_F) {
                unsigned dst = sh2b + 4u * (unsigned)(f + 4 * (f >> 3));
                CP_ASYNC4(dst, src + f);
            }
        }
    } else {
        for (int i = tid; i < TQ; i += THREADS) {
            int g0 = IB + 2 * i, g1 = g0 + 1;
            float lo = (g0 >= 0 && g0 < N) ? x[g0] : 0.0f;
            float hi = (g1 >= 0 && g1 < N) ? x[g1] : 0.0f;
            u64 d; PACK_X2(d, lo, hi);
            sh2[SPq(i)] = d;
        }
    }
    CP_COMMIT(); CP_WAIT0();
    __syncthreads();

    const int wid  = tid >> 5;
    const int lane = tid & 31;
    const int p    = wid % 3;                 // class (uniform per warp)
    const int u    = (wid / 3) * 32 + lane;   // 0..63
    const int half = (tid < 96) ? 0 : 1;      // u<32 <-> half 0
    const u64* __restrict__ T = sh_t + p * NP;

    // ---- mainloop: window base pair 12u -> slot 18u (144B, 16B aligned) ----
    const unsigned wb32 = sh2b + 144u * (unsigned)u;

    u64 wp[34];
    #pragma unroll
    for (int m = 0; m < 12; m += 2)           // preload wp[0..11]
        LDS_V2U64(wp[m], wp[m + 1], wb32 + 8u * (unsigned)(m + 2 * (m >> 2)));

    u64 acc[RR];
    #pragma unroll
    for (int r = 0; r < RR; ++r) acc[r] = 0ull;

    #pragma unroll
    for (int k = 0; k < NP; ++k) {
        if ((k & 1) == 0 && k <= 20) {        // fetch pairs (k+12, k+13)
            const int m = k + 12;
            LDS_V2U64(wp[m], wp[m + 1], wb32 + 8u * (unsigned)(m + 2 * (m >> 2)));
        }
        const u64 tp = T[k];                  // uniform -> LDS.64 broadcast
        #pragma unroll
        for (int r = 0; r < RR; ++r)
            FMA_X2(acc[r], tp, wp[k + r], acc[r]);
    }

    // ---- stage: row stride 37 (odd) -> conflict-free STS ----
    const int row = 37 * u + p;
    #pragma unroll
    for (int r = 0; r < RR; ++r) {
        float e, o; UNPACK_X2(e, o, acc[r]);
        sh_out[row + 3 * r] = e + o;
    }
    if (half == 0) BAR_HALF(1); else BAR_HALF(2);

    // ---- structured reader: thread owns row tid/3, 12 words, 3 STG.128 ----
    {
        const int r_uu  = tid / 3;
        const int r_sub = tid - 3 * r_uu;
        const int r_row = 37 * r_uu + 12 * r_sub;   // never touches a pad
        const int r_j   = 36 * r_uu + 12 * r_sub;   // multiple of 4 -> aligned

        float v[12];
        #pragma unroll
        for (int i = 0; i < 12; ++i)
            v[i] = sh_out[r_row + i];

        if (Jb + NOUT_BLK <= n_out) {
            float4* o4 = (float4*)(out + Jb + r_j);
            o4[0] = make_float4(v[0], v[1], v[2],  v[3]);
            o4[1] = make_float4(v[4], v[5], v[6],  v[7]);
            o4[2] = make_float4(v[8], v[9], v[10], v[11]);
        } else {
            #pragma unroll
            for (int i = 0; i < 12; ++i) {
                int j = Jb + r_j + i;
                if (j < n_out) out[j] = v[i];
            }
        }
    }
}

extern "C" void kernel_launch(void* const* d_in, const int* in_sizes, int n_in,
                              void* d_out, int out_size)
{
    const float* x = (const float*)d_in[0];
    const float* h = (const float*)d_in[1];
    float* out = (float*)d_out;

    const int N = in_sizes[0];
    const int n_out = out_size;
    const int grid = (n_out + NOUT_BLK - 1) / NOUT_BLK;   // 1366

    poly_resample_kernel<<<grid, THREADS>>>(x, h, out, N, n_out);
}